// round 14
// baseline (speedup 1.0000x reference)
#include <cuda_runtime.h>
#include <cuda_bf16.h>
#include <cstdint>

#define NB   64
#define LL   16
#define IS   1024
#define TT   4064
#define TPAD 4096
#define MAXL 95
#define LNEPS 1e-12f

// mma GEMM config: CTA tile 128x128, K-chunk 64, 3 terms * 16 chunks, 3 stages
#define KC        64
#define NSTG      48
#define STAGES    3
#define SROW      72                            // 72 bf16 = 144B row stride
#define TILE_BYTES (128 * SROW * 2)             // 18432
#define STG_BYTES  (2 * TILE_BYTES)             // 36864
#define SMEM_GEMM  (STAGES * STG_BYTES)         // 110592

#define KSPL  8

// ---------------- scratch (NEVER passed as kernel args from host!) -----------
__device__ float g_u[NB * IS];
__device__ float g_uv[NB * IS];
__device__ float g_c[NB];
__device__ float g_c2[NB * IS];
__device__ float g_part[2 * KSPL * NB * IS];
__device__ float g_Hm[(size_t)TPAD * IS];
__device__ __align__(256) __nv_bfloat16 g_Phi[(size_t)TPAD * IS];
__device__ __align__(256) __nv_bfloat16 g_Plo[(size_t)TPAD * IS];
__device__ __align__(256) __nv_bfloat16 g_Bhi[(size_t)IS * IS];
__device__ __align__(256) __nv_bfloat16 g_Blo[(size_t)IS * IS];
__device__ int   g_seg[TT];
__device__ int   g_pos[TT];

// ---------------- ptx helpers ------------------------------------------------
__device__ __forceinline__ uint32_t smem_u32(const void* p) {
    uint32_t a;
    asm("{ .reg .u64 t; cvta.to.shared.u64 t, %1; cvt.u32.u64 %0, t; }" : "=r"(a) : "l"(p));
    return a;
}
__device__ __forceinline__ void cp16(uint32_t dst, const void* src) {
    asm volatile("cp.async.cg.shared.global [%0], [%1], 16;" :: "r"(dst), "l"(src) : "memory");
}
#define CP_COMMIT() asm volatile("cp.async.commit_group;" ::: "memory")
#define CP_WAIT(n)  asm volatile("cp.async.wait_group %0;" :: "n"(n) : "memory")
__device__ __forceinline__ void ldm4(uint32_t* r, uint32_t addr) {
    asm volatile("ldmatrix.sync.aligned.m8n8.x4.shared.b16 {%0,%1,%2,%3}, [%4];"
        : "=r"(r[0]), "=r"(r[1]), "=r"(r[2]), "=r"(r[3]) : "r"(addr));
}
__device__ __forceinline__ void mma16816(float* c, const uint32_t* a, uint32_t b0, uint32_t b1) {
    asm volatile("mma.sync.aligned.m16n8k16.row.col.f32.bf16.bf16.f32 "
        "{%0,%1,%2,%3}, {%4,%5,%6,%7}, {%8,%9}, {%0,%1,%2,%3};"
        : "+f"(c[0]), "+f"(c[1]), "+f"(c[2]), "+f"(c[3])
        : "r"(a[0]), "r"(a[1]), "r"(a[2]), "r"(a[3]), "r"(b0), "r"(b1));
}

// ================= small kernels =============================================
__global__ void map_kernel(const int* __restrict__ l_hs) {
    __shared__ int offs[NB + 1];
    if (threadIdx.x == 0) {
        int s = 0;
        for (int b = 0; b < NB; b++) { offs[b] = s; s += l_hs[b]; }
        offs[NB] = s;
    }
    __syncthreads();
    int b = threadIdx.x;
    int o = offs[b], n = offs[b + 1] - o;
    for (int i = 0; i < n; i++) { g_seg[o + i] = b; g_pos[o + i] = i; }
}

__global__ void fill_kernel(const float4* __restrict__ beta4, float4* __restrict__ out4) {
    int i = blockIdx.x * 256 + threadIdx.x;
    out4[i] = beta4[i & 255];
}

// fused: enc_w[:, :1024] -> Bhi/Blo  AND  zero-pad Phi/Plo rows TT..TPAD
__global__ void wconv_kernel(const float* __restrict__ w) {
    int i = blockIdx.x * 256 + threadIdx.x;
    if (i < IS * IS) {
        int n = i >> 10, k = i & 1023;
        float v = w[(size_t)n * 2048 + k];
        __nv_bfloat16 h = __float2bfloat16(v);
        g_Bhi[i] = h;
        g_Blo[i] = __float2bfloat16(v - __bfloat162float(h));
    } else {
        int j = i - IS * IS;                   // 0 .. (TPAD-TT)*IS-1
        g_Phi[(size_t)TT * IS + j] = __float2bfloat16(0.f);
        g_Plo[(size_t)TT * IS + j] = __float2bfloat16(0.f);
    }
}

// ================= fused split-K ctx GEMMs (U and c2) ========================
__global__ void __launch_bounds__(256) gemmsk2_kernel(const float* __restrict__ ctx,
                                                      const float* __restrict__ W0,
                                                      const float* __restrict__ W1) {
    __shared__ float As[64][17];
    __shared__ float Ws[16][68];
    const int z = blockIdx.z;
    const float* W = z ? W1 : W0;
    const int ws = z ? 2 * IS : IS;
    const int n0 = blockIdx.x * 64;
    const int kb = blockIdx.y * (IS / KSPL);
    const int tid = threadIdx.x;
    const int tx = tid & 15, ty = tid >> 4;
    float acc[4][4] = {};
    for (int k0 = kb; k0 < kb + IS / KSPL; k0 += 16) {
        {
            int m = tid >> 2, kk = (tid & 3) << 2;
            float4 v = *reinterpret_cast<const float4*>(&ctx[m * IS + k0 + kk]);
            As[m][kk] = v.x; As[m][kk + 1] = v.y; As[m][kk + 2] = v.z; As[m][kk + 3] = v.w;
        }
        {
            int n = tid >> 2, kk = (tid & 3) << 2;
            float4 v = *reinterpret_cast<const float4*>(&W[(size_t)(n0 + n) * ws + k0 + kk]);
            Ws[kk][n] = v.x; Ws[kk + 1][n] = v.y; Ws[kk + 2][n] = v.z; Ws[kk + 3][n] = v.w;
        }
        __syncthreads();
#pragma unroll
        for (int kk = 0; kk < 16; kk++) {
            float a[4];
#pragma unroll
            for (int i = 0; i < 4; i++) a[i] = As[ty * 4 + i][kk];
            float4 bv = *reinterpret_cast<const float4*>(&Ws[kk][tx * 4]);
            float b[4] = {bv.x, bv.y, bv.z, bv.w};
#pragma unroll
            for (int i = 0; i < 4; i++)
#pragma unroll
                for (int j = 0; j < 4; j++) acc[i][j] += a[i] * b[j];
        }
        __syncthreads();
    }
    float* pp = g_part + ((size_t)z * KSPL + blockIdx.y) * (NB * IS);
#pragma unroll
    for (int i = 0; i < 4; i++)
#pragma unroll
        for (int j = 0; j < 4; j++)
            pp[(ty * 4 + i) * IS + n0 + tx * 4 + j] = acc[i][j];
}

__global__ void redUC_kernel(const float* __restrict__ Ub, const float* __restrict__ encb) {
    int i = blockIdx.x * 256 + threadIdx.x;
    float su = Ub[i & (IS - 1)], sc = encb[i & (IS - 1)];
#pragma unroll
    for (int zz = 0; zz < KSPL; zz++) {
        su += g_part[zz * (NB * IS) + i];
        sc += g_part[(KSPL + zz) * (NB * IS) + i];
    }
    g_u[i] = su;
    g_c2[i] = sc;
}

__global__ void __launch_bounds__(256) gemmskv_kernel(const float* __restrict__ W) {
    __shared__ float As[64][17];
    __shared__ float Ws[16][68];
    const int n0 = blockIdx.x * 64;
    const int kb = blockIdx.y * (IS / KSPL);
    const int tid = threadIdx.x;
    const int tx = tid & 15, ty = tid >> 4;
    float acc[4][4] = {};
    for (int k0 = kb; k0 < kb + IS / KSPL; k0 += 16) {
        {
            int m = tid >> 2, kk = (tid & 3) << 2;
            float4 v = *reinterpret_cast<const float4*>(&g_u[m * IS + k0 + kk]);
            As[m][kk] = v.x; As[m][kk + 1] = v.y; As[m][kk + 2] = v.z; As[m][kk + 3] = v.w;
        }
        {
            int k = tid >> 4, n4 = (tid & 15) << 2;
            float4 v = *reinterpret_cast<const float4*>(&W[(size_t)(k0 + k) * IS + n0 + n4]);
            *reinterpret_cast<float4*>(&Ws[k][n4]) = v;
        }
        __syncthreads();
#pragma unroll
        for (int kk = 0; kk < 16; kk++) {
            float a[4];
#pragma unroll
            for (int i = 0; i < 4; i++) a[i] = As[ty * 4 + i][kk];
            float4 bv = *reinterpret_cast<const float4*>(&Ws[kk][tx * 4]);
            float b[4] = {bv.x, bv.y, bv.z, bv.w};
#pragma unroll
            for (int i = 0; i < 4; i++)
#pragma unroll
                for (int j = 0; j < 4; j++) acc[i][j] += a[i] * b[j];
        }
        __syncthreads();
    }
    float* pp = g_part + (size_t)blockIdx.y * (NB * IS);
#pragma unroll
    for (int i = 0; i < 4; i++)
#pragma unroll
        for (int j = 0; j < 4; j++)
            pp[(ty * 4 + i) * IS + n0 + tx * 4 + j] = acc[i][j];
}

__global__ void redV_kernel() {
    int i = blockIdx.x * 256 + threadIdx.x;
    float s = 0.f;
#pragma unroll
    for (int zz = 0; zz < KSPL; zz++) s += g_part[zz * (NB * IS) + i];
    g_uv[i] = s;
}

__global__ void cdot_kernel(const float* __restrict__ Vb) {
    int wid = threadIdx.x >> 5, lane = threadIdx.x & 31;
    int b = blockIdx.x * 8 + wid;
    float s = 0.f;
    for (int k = lane; k < IS; k += 32) s += g_u[b * IS + k] * Vb[k];
#pragma unroll
    for (int o = 16; o; o >>= 1) s += __shfl_xor_sync(0xffffffffu, s, o);
    if (lane == 0) g_c[b] = s;
}

// ================= attention -> Phi/Plo ======================================
__global__ void __launch_bounds__(256) attn_kernel(const float* __restrict__ wemb) {
    extern __shared__ float sw[];
    __shared__ float ssc[32];
    const int t = blockIdx.x;
    const int tid = threadIdx.x;
    const int seg = g_seg[t];
    {
        const float4* wt4 = reinterpret_cast<const float4*>(wemb + (size_t)t * LL * IS);
        float4* sw4 = reinterpret_cast<float4*>(sw);
        for (int i = tid; i < LL * IS / 4; i += 256) sw4[i] = wt4[i];
    }
    __syncthreads();
    const float* uvp = g_uv + seg * IS;
    const int wid = tid >> 5, lane = tid & 31;
    for (int l = wid; l < LL; l += 8) {
        float s = 0.f;
        const float* row = sw + l * IS;
        for (int k = lane; k < IS; k += 32) s += row[k] * uvp[k];
#pragma unroll
        for (int o = 16; o; o >>= 1) s += __shfl_xor_sync(0xffffffffu, s, o);
        if (lane == 0) ssc[l] = s + g_c[seg];
    }
    __syncthreads();
    if (tid < 32) {
        float v = (lane < LL) ? ssc[lane] : -3.0e38f;
        float m = v;
#pragma unroll
        for (int o = 16; o; o >>= 1) m = fmaxf(m, __shfl_xor_sync(0xffffffffu, m, o));
        float e = (lane < LL) ? __expf(v - m) : 0.f;
        float s = e;
#pragma unroll
        for (int o = 16; o; o >>= 1) s += __shfl_xor_sync(0xffffffffu, s, o);
        if (lane < LL) ssc[lane] = e / s;
    }
    __syncthreads();
    float at[LL];
#pragma unroll
    for (int l = 0; l < LL; l++) at[l] = ssc[l];
    const int d0 = tid * 4;
    float acc[4] = {};
#pragma unroll
    for (int l = 0; l < LL; l++) {
        const float4 a = *reinterpret_cast<const float4*>(&sw[l * IS + d0]);
        acc[0] += at[l] * a.x; acc[1] += at[l] * a.y;
        acc[2] += at[l] * a.z; acc[3] += at[l] * a.w;
    }
    __nv_bfloat16 h[4];
#pragma unroll
    for (int q = 0; q < 4; q++) h[q] = __float2bfloat16(acc[q]);
    __nv_bfloat162* ph2 = reinterpret_cast<__nv_bfloat162*>(g_Phi + (size_t)t * IS + d0);
    ph2[0] = __nv_bfloat162(h[0], h[1]);
    ph2[1] = __nv_bfloat162(h[2], h[3]);
    __nv_bfloat162* pl2 = reinterpret_cast<__nv_bfloat162*>(g_Plo + (size_t)t * IS + d0);
    pl2[0] = __nv_bfloat162(__float2bfloat16(acc[0] - __bfloat162float(h[0])),
                            __float2bfloat16(acc[1] - __bfloat162float(h[1])));
    pl2[1] = __nv_bfloat162(__float2bfloat16(acc[2] - __bfloat162float(h[2])),
                            __float2bfloat16(acc[3] - __bfloat162float(h[3])));
}

// ================= mma GEMM (ldmatrix fragments; KC=64, 3-stage) =============
__global__ void __launch_bounds__(256, 2) gemm_mma_kernel() {
    extern __shared__ __nv_bfloat16 smbuf[];
    const uint32_t sb = smem_u32(smbuf);
    const int tid = threadIdx.x, lane = tid & 31, w = tid >> 5;
    const int m0 = blockIdx.y * 128, n0 = blockIdx.x * 128;
    const int wm = (w & 1) * 64, wn = (w >> 1) * 32;
    const int lr = tid >> 1;                 // load row 0..127
    const int lb = (tid & 1) * 64;           // load byte base 0 or 64
    // ldmatrix lane addressing: rows via lane&15, k+8 half via lane>>4
    const uint32_t lrow16 = (uint32_t)(lane & 15) * (SROW * 2);
    const uint32_t lhi = (uint32_t)(lane >> 4) * 16;
    float acc[4][4][4] = {};

    auto load_stage = [&](int j) {
        const int term = j >> 4;
        const int kk = (j & 15) * KC;
        const __nv_bfloat16* Ap = ((term == 2) ? g_Plo : g_Phi) + (size_t)(m0 + lr) * IS + kk;
        const __nv_bfloat16* Bp = ((term == 1) ? g_Blo : g_Bhi) + (size_t)(n0 + lr) * IS + kk;
        const int slot = j % STAGES;
        const uint32_t base = sb + slot * STG_BYTES + lr * (SROW * 2) + lb;
        const int eo = lb / 2;
#pragma unroll
        for (int c = 0; c < 4; c++) {
            cp16(base + c * 16, Ap + eo + c * 8);
            cp16(base + TILE_BYTES + c * 16, Bp + eo + c * 8);
        }
    };

#pragma unroll
    for (int j = 0; j < STAGES - 1; j++) { load_stage(j); CP_COMMIT(); }
    for (int i = 0; i < NSTG; i++) {
        if (i + STAGES - 1 < NSTG) load_stage(i + STAGES - 1);
        CP_COMMIT();
        CP_WAIT(STAGES - 2);
        __syncthreads();
        const int slot = i % STAGES;
        const uint32_t sA = sb + slot * STG_BYTES;
        const uint32_t sB = sA + TILE_BYTES;
#pragma unroll
        for (int k16 = 0; k16 < KC / 16; k16++) {
            const uint32_t kbyte = (uint32_t)k16 * 32;
            uint32_t a[4][4], bb[2][4];
#pragma unroll
            for (int mt = 0; mt < 4; mt++)
                ldm4(a[mt], sA + (wm + mt * 16) * (SROW * 2) + lrow16 + kbyte + lhi);
#pragma unroll
            for (int ntp = 0; ntp < 2; ntp++)
                ldm4(bb[ntp], sB + (wn + ntp * 16) * (SROW * 2) + lrow16 + kbyte + lhi);
#pragma unroll
            for (int mt = 0; mt < 4; mt++)
#pragma unroll
                for (int nt = 0; nt < 4; nt++)
                    mma16816(acc[mt][nt], a[mt], bb[nt >> 1][nt & 1], bb[nt >> 1][(nt & 1) + 2]);
        }
        __syncthreads();
    }

#pragma unroll
    for (int mt = 0; mt < 4; mt++) {
        int m = m0 + wm + mt * 16 + (lane >> 2);
#pragma unroll
        for (int nt = 0; nt < 4; nt++) {
            int n = n0 + wn + nt * 8 + (lane & 3) * 2;
            if (m < TT)
                *reinterpret_cast<float2*>(&g_Hm[(size_t)m * IS + n]) =
                    make_float2(acc[mt][nt][0], acc[mt][nt][1]);
            if (m + 8 < TT)
                *reinterpret_cast<float2*>(&g_Hm[(size_t)(m + 8) * IS + n]) =
                    make_float2(acc[mt][nt][2], acc[mt][nt][3]);
        }
    }
}

// ---------------- LayerNorm(Hm + c2[seg]) + ragged scatter --------------------
__global__ void __launch_bounds__(256) ln_kernel(const float* __restrict__ gamma,
                                                 const float* __restrict__ beta,
                                                 float* __restrict__ out) {
    __shared__ float rs[8], rs2[8];
    __shared__ float hv[IS];
    const int t = blockIdx.x;
    const int tid = threadIdx.x;
    const int seg = g_seg[t];
    const float* hm = g_Hm + (size_t)t * IS;
    const float* c2 = g_c2 + (size_t)seg * IS;
    float s = 0.f, s2 = 0.f;
    for (int d = tid; d < IS; d += 256) {
        float v = hm[d] + c2[d];
        hv[d] = v;
        s += v; s2 += v * v;
    }
    const int wid = tid >> 5, lane = tid & 31;
#pragma unroll
    for (int o = 16; o; o >>= 1) {
        s  += __shfl_xor_sync(0xffffffffu, s, o);
        s2 += __shfl_xor_sync(0xffffffffu, s2, o);
    }
    if (lane == 0) { rs[wid] = s; rs2[wid] = s2; }
    __syncthreads();
    if (tid == 0) {
        float S = 0.f, S2 = 0.f;
        for (int w = 0; w < 8; w++) { S += rs[w]; S2 += rs2[w]; }
        rs[0] = S; rs2[0] = S2;
    }
    __syncthreads();
    const float mean = rs[0] * (1.0f / IS);
    const float var  = rs2[0] * (1.0f / IS) - mean * mean;
    const float inv  = rsqrtf(var + LNEPS);
    float* orow = out + ((size_t)(seg * MAXL + g_pos[t])) * IS;
    for (int d = tid; d < IS; d += 256)
        orow[d] = gamma[d] * (hv[d] - mean) * inv + beta[d];
}

// ---------------- launch ------------------------------------------------------
extern "C" void kernel_launch(void* const* d_in, const int* in_sizes, int n_in,
                              void* d_out, int out_size) {
    const float* ctx   = (const float*)d_in[0];
    const float* wemb  = (const float*)d_in[1];
    const int*   l_hs  = (const int*)  d_in[3];
    const float* U_w   = (const float*)d_in[n_in - 8];
    const float* U_b   = (const float*)d_in[n_in - 7];
    const float* V_w   = (const float*)d_in[n_in - 6];
    const float* V_b   = (const float*)d_in[n_in - 5];
    const float* enc_w = (const float*)d_in[n_in - 4];
    const float* enc_b = (const float*)d_in[n_in - 3];
    const float* gamma = (const float*)d_in[n_in - 2];
    const float* beta  = (const float*)d_in[n_in - 1];
    float* out = (float*)d_out;

    cudaFuncSetAttribute(attn_kernel, cudaFuncAttributeMaxDynamicSharedMemorySize, LL * IS * 4);
    cudaFuncSetAttribute(gemm_mma_kernel, cudaFuncAttributeMaxDynamicSharedMemorySize, SMEM_GEMM);

    map_kernel<<<1, NB>>>(l_hs);
    fill_kernel<<<(NB * MAXL * IS / 4) / 256, 256>>>((const float4*)beta, (float4*)out);
    wconv_kernel<<<(IS * IS + (TPAD - TT) * IS) / 256, 256>>>(enc_w);

    gemmsk2_kernel<<<dim3(IS / 64, KSPL, 2), 256>>>(ctx, U_w, enc_w + IS);
    redUC_kernel<<<(NB * IS) / 256, 256>>>(U_b, enc_b);
    cdot_kernel<<<NB / 8, 256>>>(V_b);
    gemmskv_kernel<<<dim3(IS / 64, KSPL), 256>>>(V_w);
    redV_kernel<<<(NB * IS) / 256, 256>>>();

    attn_kernel<<<TT, 256, LL * IS * 4>>>(wemb);
    gemm_mma_kernel<<<dim3(IS / 128, TPAD / 128), 256, SMEM_GEMM>>>();
    ln_kernel<<<TT, 256>>>(gamma, beta, out);
}

// round 15
// speedup vs baseline: 1.4007x; 1.4007x over previous
#include <cuda_runtime.h>
#include <cuda_bf16.h>
#include <cstdint>

#define NB   64
#define LL   16
#define IS   1024
#define TT   4064
#define TPAD 4096
#define MAXL 95
#define LNEPS 1e-12f

// mma GEMM config: CTA tile 128x128, K-chunk 64, 3 terms * 16 chunks, 3 stages
#define KC        64
#define NSTG      48
#define STAGES    3
#define SROW      72                            // 72 bf16 = 144B row stride
#define TILE_BYTES (128 * SROW * 2)             // 18432
#define STG_BYTES  (2 * TILE_BYTES)             // 36864
#define SMEM_GEMM  (STAGES * STG_BYTES)         // 110592

#define KSPL  8

// ---------------- scratch (NEVER passed as kernel args from host!) -----------
__device__ float g_u[NB * IS];
__device__ float g_uv[NB * IS];
__device__ float g_c[NB];
__device__ float g_c2[NB * IS];
__device__ float g_part[2 * KSPL * NB * IS];
__device__ float g_Hm[(size_t)TPAD * IS];
__device__ __align__(256) __nv_bfloat16 g_Phi[(size_t)TPAD * IS];
__device__ __align__(256) __nv_bfloat16 g_Plo[(size_t)TPAD * IS];
__device__ __align__(256) __nv_bfloat16 g_Bhi[(size_t)IS * IS];
__device__ __align__(256) __nv_bfloat16 g_Blo[(size_t)IS * IS];
__device__ int   g_seg[TT];
__device__ int   g_pos[TT];

// ---------------- ptx helpers ------------------------------------------------
__device__ __forceinline__ uint32_t smem_u32(const void* p) {
    uint32_t a;
    asm("{ .reg .u64 t; cvta.to.shared.u64 t, %1; cvt.u32.u64 %0, t; }" : "=r"(a) : "l"(p));
    return a;
}
__device__ __forceinline__ void cp16(uint32_t dst, const void* src) {
    asm volatile("cp.async.cg.shared.global [%0], [%1], 16;" :: "r"(dst), "l"(src) : "memory");
}
#define CP_COMMIT() asm volatile("cp.async.commit_group;" ::: "memory")
#define CP_WAIT(n)  asm volatile("cp.async.wait_group %0;" :: "n"(n) : "memory")
__device__ __forceinline__ void ldm4(uint32_t* r, uint32_t addr) {
    asm volatile("ldmatrix.sync.aligned.m8n8.x4.shared.b16 {%0,%1,%2,%3}, [%4];"
        : "=r"(r[0]), "=r"(r[1]), "=r"(r[2]), "=r"(r[3]) : "r"(addr));
}
__device__ __forceinline__ void mma16816(float* c, const uint32_t* a, uint32_t b0, uint32_t b1) {
    asm volatile("mma.sync.aligned.m16n8k16.row.col.f32.bf16.bf16.f32 "
        "{%0,%1,%2,%3}, {%4,%5,%6,%7}, {%8,%9}, {%0,%1,%2,%3};"
        : "+f"(c[0]), "+f"(c[1]), "+f"(c[2]), "+f"(c[3])
        : "r"(a[0]), "r"(a[1]), "r"(a[2]), "r"(a[3]), "r"(b0), "r"(b1));
}

// ================= small kernels =============================================
__global__ void map_kernel(const int* __restrict__ l_hs) {
    __shared__ int offs[NB + 1];
    if (threadIdx.x == 0) {
        int s = 0;
        for (int b = 0; b < NB; b++) { offs[b] = s; s += l_hs[b]; }
        offs[NB] = s;
    }
    __syncthreads();
    int b = threadIdx.x;
    int o = offs[b], n = offs[b + 1] - o;
    for (int i = 0; i < n; i++) { g_seg[o + i] = b; g_pos[o + i] = i; }
}

__global__ void fill_kernel(const float4* __restrict__ beta4, float4* __restrict__ out4) {
    int i = blockIdx.x * 256 + threadIdx.x;
    out4[i] = beta4[i & 255];
}

// fused: enc_w[:, :1024] -> Bhi/Blo  AND  zero-pad Phi/Plo rows TT..TPAD
__global__ void wconv_kernel(const float* __restrict__ w) {
    int i = blockIdx.x * 256 + threadIdx.x;
    if (i < IS * IS) {
        int n = i >> 10, k = i & 1023;
        float v = w[(size_t)n * 2048 + k];
        __nv_bfloat16 h = __float2bfloat16(v);
        g_Bhi[i] = h;
        g_Blo[i] = __float2bfloat16(v - __bfloat162float(h));
    } else {
        int j = i - IS * IS;
        g_Phi[(size_t)TT * IS + j] = __float2bfloat16(0.f);
        g_Plo[(size_t)TT * IS + j] = __float2bfloat16(0.f);
    }
}

// ================= fused split-K ctx GEMMs (U and c2) ========================
__global__ void __launch_bounds__(256) gemmsk2_kernel(const float* __restrict__ ctx,
                                                      const float* __restrict__ W0,
                                                      const float* __restrict__ W1) {
    __shared__ float As[64][17];
    __shared__ float Ws[16][68];
    const int z = blockIdx.z;
    const float* W = z ? W1 : W0;
    const int ws = z ? 2 * IS : IS;
    const int n0 = blockIdx.x * 64;
    const int kb = blockIdx.y * (IS / KSPL);
    const int tid = threadIdx.x;
    const int tx = tid & 15, ty = tid >> 4;
    float acc[4][4] = {};
    for (int k0 = kb; k0 < kb + IS / KSPL; k0 += 16) {
        {
            int m = tid >> 2, kk = (tid & 3) << 2;
            float4 v = *reinterpret_cast<const float4*>(&ctx[m * IS + k0 + kk]);
            As[m][kk] = v.x; As[m][kk + 1] = v.y; As[m][kk + 2] = v.z; As[m][kk + 3] = v.w;
        }
        {
            int n = tid >> 2, kk = (tid & 3) << 2;
            float4 v = *reinterpret_cast<const float4*>(&W[(size_t)(n0 + n) * ws + k0 + kk]);
            Ws[kk][n] = v.x; Ws[kk + 1][n] = v.y; Ws[kk + 2][n] = v.z; Ws[kk + 3][n] = v.w;
        }
        __syncthreads();
#pragma unroll
        for (int kk = 0; kk < 16; kk++) {
            float a[4];
#pragma unroll
            for (int i = 0; i < 4; i++) a[i] = As[ty * 4 + i][kk];
            float4 bv = *reinterpret_cast<const float4*>(&Ws[kk][tx * 4]);
            float b[4] = {bv.x, bv.y, bv.z, bv.w};
#pragma unroll
            for (int i = 0; i < 4; i++)
#pragma unroll
                for (int j = 0; j < 4; j++) acc[i][j] += a[i] * b[j];
        }
        __syncthreads();
    }
    float* pp = g_part + ((size_t)z * KSPL + blockIdx.y) * (NB * IS);
#pragma unroll
    for (int i = 0; i < 4; i++)
#pragma unroll
        for (int j = 0; j < 4; j++)
            pp[(ty * 4 + i) * IS + n0 + tx * 4 + j] = acc[i][j];
}

__global__ void redUC_kernel(const float* __restrict__ Ub, const float* __restrict__ encb) {
    int i = blockIdx.x * 256 + threadIdx.x;
    float su = Ub[i & (IS - 1)], sc = encb[i & (IS - 1)];
#pragma unroll
    for (int zz = 0; zz < KSPL; zz++) {
        su += g_part[zz * (NB * IS) + i];
        sc += g_part[(KSPL + zz) * (NB * IS) + i];
    }
    g_u[i] = su;
    g_c2[i] = sc;
}

__global__ void __launch_bounds__(256) gemmskv_kernel(const float* __restrict__ W) {
    __shared__ float As[64][17];
    __shared__ float Ws[16][68];
    const int n0 = blockIdx.x * 64;
    const int kb = blockIdx.y * (IS / KSPL);
    const int tid = threadIdx.x;
    const int tx = tid & 15, ty = tid >> 4;
    float acc[4][4] = {};
    for (int k0 = kb; k0 < kb + IS / KSPL; k0 += 16) {
        {
            int m = tid >> 2, kk = (tid & 3) << 2;
            float4 v = *reinterpret_cast<const float4*>(&g_u[m * IS + k0 + kk]);
            As[m][kk] = v.x; As[m][kk + 1] = v.y; As[m][kk + 2] = v.z; As[m][kk + 3] = v.w;
        }
        {
            int k = tid >> 4, n4 = (tid & 15) << 2;
            float4 v = *reinterpret_cast<const float4*>(&W[(size_t)(k0 + k) * IS + n0 + n4]);
            *reinterpret_cast<float4*>(&Ws[k][n4]) = v;
        }
        __syncthreads();
#pragma unroll
        for (int kk = 0; kk < 16; kk++) {
            float a[4];
#pragma unroll
            for (int i = 0; i < 4; i++) a[i] = As[ty * 4 + i][kk];
            float4 bv = *reinterpret_cast<const float4*>(&Ws[kk][tx * 4]);
            float b[4] = {bv.x, bv.y, bv.z, bv.w};
#pragma unroll
            for (int i = 0; i < 4; i++)
#pragma unroll
                for (int j = 0; j < 4; j++) acc[i][j] += a[i] * b[j];
        }
        __syncthreads();
    }
    float* pp = g_part + (size_t)blockIdx.y * (NB * IS);
#pragma unroll
    for (int i = 0; i < 4; i++)
#pragma unroll
        for (int j = 0; j < 4; j++)
            pp[(ty * 4 + i) * IS + n0 + tx * 4 + j] = acc[i][j];
}

__global__ void redV_kernel() {
    int i = blockIdx.x * 256 + threadIdx.x;
    float s = 0.f;
#pragma unroll
    for (int zz = 0; zz < KSPL; zz++) s += g_part[zz * (NB * IS) + i];
    g_uv[i] = s;
}

__global__ void cdot_kernel(const float* __restrict__ Vb) {
    int wid = threadIdx.x >> 5, lane = threadIdx.x & 31;
    int b = blockIdx.x * 8 + wid;
    float s = 0.f;
    for (int k = lane; k < IS; k += 32) s += g_u[b * IS + k] * Vb[k];
#pragma unroll
    for (int o = 16; o; o >>= 1) s += __shfl_xor_sync(0xffffffffu, s, o);
    if (lane == 0) g_c[b] = s;
}

// ================= attention -> Phi/Plo ======================================
__global__ void __launch_bounds__(256) attn_kernel(const float* __restrict__ wemb) {
    extern __shared__ float sw[];
    __shared__ float ssc[32];
    const int t = blockIdx.x;
    const int tid = threadIdx.x;
    const int seg = g_seg[t];
    {
        const float4* wt4 = reinterpret_cast<const float4*>(wemb + (size_t)t * LL * IS);
        float4* sw4 = reinterpret_cast<float4*>(sw);
        for (int i = tid; i < LL * IS / 4; i += 256) sw4[i] = wt4[i];
    }
    __syncthreads();
    const float* uvp = g_uv + seg * IS;
    const int wid = tid >> 5, lane = tid & 31;
    for (int l = wid; l < LL; l += 8) {
        float s = 0.f;
        const float* row = sw + l * IS;
        for (int k = lane; k < IS; k += 32) s += row[k] * uvp[k];
#pragma unroll
        for (int o = 16; o; o >>= 1) s += __shfl_xor_sync(0xffffffffu, s, o);
        if (lane == 0) ssc[l] = s + g_c[seg];
    }
    __syncthreads();
    if (tid < 32) {
        float v = (lane < LL) ? ssc[lane] : -3.0e38f;
        float m = v;
#pragma unroll
        for (int o = 16; o; o >>= 1) m = fmaxf(m, __shfl_xor_sync(0xffffffffu, m, o));
        float e = (lane < LL) ? __expf(v - m) : 0.f;
        float s = e;
#pragma unroll
        for (int o = 16; o; o >>= 1) s += __shfl_xor_sync(0xffffffffu, s, o);
        if (lane < LL) ssc[lane] = e / s;
    }
    __syncthreads();
    float at[LL];
#pragma unroll
    for (int l = 0; l < LL; l++) at[l] = ssc[l];
    const int d0 = tid * 4;
    float acc[4] = {};
#pragma unroll
    for (int l = 0; l < LL; l++) {
        const float4 a = *reinterpret_cast<const float4*>(&sw[l * IS + d0]);
        acc[0] += at[l] * a.x; acc[1] += at[l] * a.y;
        acc[2] += at[l] * a.z; acc[3] += at[l] * a.w;
    }
    __nv_bfloat16 h[4];
#pragma unroll
    for (int q = 0; q < 4; q++) h[q] = __float2bfloat16(acc[q]);
    __nv_bfloat162* ph2 = reinterpret_cast<__nv_bfloat162*>(g_Phi + (size_t)t * IS + d0);
    ph2[0] = __nv_bfloat162(h[0], h[1]);
    ph2[1] = __nv_bfloat162(h[2], h[3]);
    __nv_bfloat162* pl2 = reinterpret_cast<__nv_bfloat162*>(g_Plo + (size_t)t * IS + d0);
    pl2[0] = __nv_bfloat162(__float2bfloat16(acc[0] - __bfloat162float(h[0])),
                            __float2bfloat16(acc[1] - __bfloat162float(h[1])));
    pl2[1] = __nv_bfloat162(__float2bfloat16(acc[2] - __bfloat162float(h[2])),
                            __float2bfloat16(acc[3] - __bfloat162float(h[3])));
}

// ================= mma GEMM (ldmatrix; KC=64, 3-stage; NO occupancy cap) =====
__global__ void __launch_bounds__(256) gemm_mma_kernel() {
    extern __shared__ __nv_bfloat16 smbuf[];
    const uint32_t sb = smem_u32(smbuf);
    const int tid = threadIdx.x, lane = tid & 31, w = tid >> 5;
    const int m0 = blockIdx.y * 128, n0 = blockIdx.x * 128;
    const int wm = (w & 1) * 64, wn = (w >> 1) * 32;
    const int lr = tid >> 1;
    const int lb = (tid & 1) * 64;
    const uint32_t lrow16 = (uint32_t)(lane & 15) * (SROW * 2);
    const uint32_t lhi = (uint32_t)(lane >> 4) * 16;
    float acc[4][4][4] = {};

    auto load_stage = [&](int j) {
        const int term = j >> 4;
        const int kk = (j & 15) * KC;
        const __nv_bfloat16* Ap = ((term == 2) ? g_Plo : g_Phi) + (size_t)(m0 + lr) * IS + kk;
        const __nv_bfloat16* Bp = ((term == 1) ? g_Blo : g_Bhi) + (size_t)(n0 + lr) * IS + kk;
        const int slot = j % STAGES;
        const uint32_t base = sb + slot * STG_BYTES + lr * (SROW * 2) + lb;
        const int eo = lb / 2;
#pragma unroll
        for (int c = 0; c < 4; c++) {
            cp16(base + c * 16, Ap + eo + c * 8);
            cp16(base + TILE_BYTES + c * 16, Bp + eo + c * 8);
        }
    };

#pragma unroll
    for (int j = 0; j < STAGES - 1; j++) { load_stage(j); CP_COMMIT(); }
    for (int i = 0; i < NSTG; i++) {
        if (i + STAGES - 1 < NSTG) load_stage(i + STAGES - 1);
        CP_COMMIT();
        CP_WAIT(STAGES - 2);
        __syncthreads();
        const int slot = i % STAGES;
        const uint32_t sA = sb + slot * STG_BYTES;
        const uint32_t sB = sA + TILE_BYTES;
#pragma unroll
        for (int k16 = 0; k16 < KC / 16; k16++) {
            const uint32_t kbyte = (uint32_t)k16 * 32;
            uint32_t a[4][4], bb[2][4];
#pragma unroll
            for (int mt = 0; mt < 4; mt++)
                ldm4(a[mt], sA + (wm + mt * 16) * (SROW * 2) + lrow16 + kbyte + lhi);
#pragma unroll
            for (int ntp = 0; ntp < 2; ntp++)
                ldm4(bb[ntp], sB + (wn + ntp * 16) * (SROW * 2) + lrow16 + kbyte + lhi);
#pragma unroll
            for (int mt = 0; mt < 4; mt++)
#pragma unroll
                for (int nt = 0; nt < 4; nt++)
                    mma16816(acc[mt][nt], a[mt], bb[nt >> 1][nt & 1], bb[nt >> 1][(nt & 1) + 2]);
        }
        __syncthreads();
    }

#pragma unroll
    for (int mt = 0; mt < 4; mt++) {
        int m = m0 + wm + mt * 16 + (lane >> 2);
#pragma unroll
        for (int nt = 0; nt < 4; nt++) {
            int n = n0 + wn + nt * 8 + (lane & 3) * 2;
            if (m < TT)
                *reinterpret_cast<float2*>(&g_Hm[(size_t)m * IS + n]) =
                    make_float2(acc[mt][nt][0], acc[mt][nt][1]);
            if (m + 8 < TT)
                *reinterpret_cast<float2*>(&g_Hm[(size_t)(m + 8) * IS + n]) =
                    make_float2(acc[mt][nt][2], acc[mt][nt][3]);
        }
    }
}

// ---------------- LayerNorm(Hm + c2[seg]) + ragged scatter --------------------
__global__ void __launch_bounds__(256) ln_kernel(const float* __restrict__ gamma,
                                                 const float* __restrict__ beta,
                                                 float* __restrict__ out) {
    __shared__ float rs[8], rs2[8];
    __shared__ float hv[IS];
    const int t = blockIdx.x;
    const int tid = threadIdx.x;
    const int seg = g_seg[t];
    const float* hm = g_Hm + (size_t)t * IS;
    const float* c2 = g_c2 + (size_t)seg * IS;
    float s = 0.f, s2 = 0.f;
    for (int d = tid; d < IS; d += 256) {
        float v = hm[d] + c2[d];
        hv[d] = v;
        s += v; s2 += v * v;
    }
    const int wid = tid >> 5, lane = tid & 31;
#pragma unroll
    for (int o = 16; o; o >>= 1) {
        s  += __shfl_xor_sync(0xffffffffu, s, o);
        s2 += __shfl_xor_sync(0xffffffffu, s2, o);
    }
    if (lane == 0) { rs[wid] = s; rs2[wid] = s2; }
    __syncthreads();
    if (tid == 0) {
        float S = 0.f, S2 = 0.f;
        for (int w = 0; w < 8; w++) { S += rs[w]; S2 += rs2[w]; }
        rs[0] = S; rs2[0] = S2;
    }
    __syncthreads();
    const float mean = rs[0] * (1.0f / IS);
    const float var  = rs2[0] * (1.0f / IS) - mean * mean;
    const float inv  = rsqrtf(var + LNEPS);
    float* orow = out + ((size_t)(seg * MAXL + g_pos[t])) * IS;
    for (int d = tid; d < IS; d += 256)
        orow[d] = gamma[d] * (hv[d] - mean) * inv + beta[d];
}

// ---------------- launch ------------------------------------------------------
extern "C" void kernel_launch(void* const* d_in, const int* in_sizes, int n_in,
                              void* d_out, int out_size) {
    const float* ctx   = (const float*)d_in[0];
    const float* wemb  = (const float*)d_in[1];
    const int*   l_hs  = (const int*)  d_in[3];
    const float* U_w   = (const float*)d_in[n_in - 8];
    const float* U_b   = (const float*)d_in[n_in - 7];
    const float* V_w   = (const float*)d_in[n_in - 6];
    const float* V_b   = (const float*)d_in[n_in - 5];
    const float* enc_w = (const float*)d_in[n_in - 4];
    const float* enc_b = (const float*)d_in[n_in - 3];
    const float* gamma = (const float*)d_in[n_in - 2];
    const float* beta  = (const float*)d_in[n_in - 1];
    float* out = (float*)d_out;

    cudaFuncSetAttribute(attn_kernel, cudaFuncAttributeMaxDynamicSharedMemorySize, LL * IS * 4);
    cudaFuncSetAttribute(gemm_mma_kernel, cudaFuncAttributeMaxDynamicSharedMemorySize, SMEM_GEMM);

    map_kernel<<<1, NB>>>(l_hs);
    fill_kernel<<<(NB * MAXL * IS / 4) / 256, 256>>>((const float4*)beta, (float4*)out);
    wconv_kernel<<<(IS * IS + (TPAD - TT) * IS) / 256, 256>>>(enc_w);

    gemmsk2_kernel<<<dim3(IS / 64, KSPL, 2), 256>>>(ctx, U_w, enc_w + IS);
    redUC_kernel<<<(NB * IS) / 256, 256>>>(U_b, enc_b);
    cdot_kernel<<<NB / 8, 256>>>(V_b);
    gemmskv_kernel<<<dim3(IS / 64, KSPL), 256>>>(V_w);
    redV_kernel<<<(NB * IS) / 256, 256>>>();

    attn_kernel<<<TT, 256, LL * IS * 4>>>(wemb);
    gemm_mma_kernel<<<dim3(IS / 128, TPAD / 128), 256, SMEM_GEMM>>>();
    ln_kernel<<<TT, 256>>>(gamma, beta, out);
}

// round 16
// speedup vs baseline: 1.5059x; 1.0752x over previous
#include <cuda_runtime.h>
#include <cuda_bf16.h>
#include <cstdint>

#define NB   64
#define LL   16
#define IS   1024
#define TT   4064
#define TPAD 4096
#define MAXL 95
#define LNEPS 1e-12f

// mma GEMM: CTA tile 128x128, per-chunk [Ahi|Alo|Bhi|Blo], 16 chunks, 2 stages
#define KC        64
#define NCHUNK    16
#define STAGES    2
#define SROW      72                            // 72 bf16 = 144B row stride
#define TILE_BYTES (128 * SROW * 2)             // 18432
#define STG_BYTES  (4 * TILE_BYTES)             // 73728
#define SMEM_GEMM  (STAGES * STG_BYTES)         // 147456

#define KSPL  8

// ---------------- scratch (NEVER passed as kernel args from host!) -----------
__device__ float g_u[NB * IS];
__device__ float g_uv[NB * IS];
__device__ float g_c2[NB * IS];
__device__ float g_part[2 * KSPL * NB * IS];
__device__ float g_Hm[(size_t)TPAD * IS];
__device__ __align__(256) __nv_bfloat16 g_Phi[(size_t)TPAD * IS];
__device__ __align__(256) __nv_bfloat16 g_Plo[(size_t)TPAD * IS];
__device__ __align__(256) __nv_bfloat16 g_Bhi[(size_t)IS * IS];
__device__ __align__(256) __nv_bfloat16 g_Blo[(size_t)IS * IS];
__device__ int   g_seg[TT];
__device__ int   g_pos[TT];

// ---------------- ptx helpers ------------------------------------------------
__device__ __forceinline__ uint32_t smem_u32(const void* p) {
    uint32_t a;
    asm("{ .reg .u64 t; cvta.to.shared.u64 t, %1; cvt.u32.u64 %0, t; }" : "=r"(a) : "l"(p));
    return a;
}
__device__ __forceinline__ void cp16(uint32_t dst, const void* src) {
    asm volatile("cp.async.cg.shared.global [%0], [%1], 16;" :: "r"(dst), "l"(src) : "memory");
}
#define CP_COMMIT() asm volatile("cp.async.commit_group;" ::: "memory")
#define CP_WAIT(n)  asm volatile("cp.async.wait_group %0;" :: "n"(n) : "memory")
__device__ __forceinline__ void ldm4(uint32_t* r, uint32_t addr) {
    asm volatile("ldmatrix.sync.aligned.m8n8.x4.shared.b16 {%0,%1,%2,%3}, [%4];"
        : "=r"(r[0]), "=r"(r[1]), "=r"(r[2]), "=r"(r[3]) : "r"(addr));
}
__device__ __forceinline__ void mma16816(float* c, const uint32_t* a, uint32_t b0, uint32_t b1) {
    asm volatile("mma.sync.aligned.m16n8k16.row.col.f32.bf16.bf16.f32 "
        "{%0,%1,%2,%3}, {%4,%5,%6,%7}, {%8,%9}, {%0,%1,%2,%3};"
        : "+f"(c[0]), "+f"(c[1]), "+f"(c[2]), "+f"(c[3])
        : "r"(a[0]), "r"(a[1]), "r"(a[2]), "r"(a[3]), "r"(b0), "r"(b1));
}

// ================= small kernels =============================================
__global__ void map_kernel(const int* __restrict__ l_hs) {
    __shared__ int offs[NB + 1];
    if (threadIdx.x == 0) {
        int s = 0;
        for (int b = 0; b < NB; b++) { offs[b] = s; s += l_hs[b]; }
        offs[NB] = s;
    }
    __syncthreads();
    int b = threadIdx.x;
    int o = offs[b], n = offs[b + 1] - o;
    for (int i = 0; i < n; i++) { g_seg[o + i] = b; g_pos[o + i] = i; }
}

__global__ void fill_kernel(const float4* __restrict__ beta4, float4* __restrict__ out4) {
    int i = blockIdx.x * 256 + threadIdx.x;
    out4[i] = beta4[i & 255];
}

// fused: enc_w[:, :1024] -> Bhi/Blo AND zero-pad Phi/Plo rows TT..TPAD
__global__ void wconv_kernel(const float* __restrict__ w) {
    int i = blockIdx.x * 256 + threadIdx.x;
    if (i < IS * IS) {
        int n = i >> 10, k = i & 1023;
        float v = w[(size_t)n * 2048 + k];
        __nv_bfloat16 h = __float2bfloat16(v);
        g_Bhi[i] = h;
        g_Blo[i] = __float2bfloat16(v - __bfloat162float(h));
    } else {
        int j = i - IS * IS;
        g_Phi[(size_t)TT * IS + j] = __float2bfloat16(0.f);
        g_Plo[(size_t)TT * IS + j] = __float2bfloat16(0.f);
    }
}

// ================= fused split-K ctx GEMMs (U and c2) ========================
__global__ void __launch_bounds__(256) gemmsk2_kernel(const float* __restrict__ ctx,
                                                      const float* __restrict__ W0,
                                                      const float* __restrict__ W1) {
    __shared__ float As[64][17];
    __shared__ float Ws[16][68];
    const int z = blockIdx.z;
    const float* W = z ? W1 : W0;
    const int ws = z ? 2 * IS : IS;
    const int n0 = blockIdx.x * 64;
    const int kb = blockIdx.y * (IS / KSPL);
    const int tid = threadIdx.x;
    const int tx = tid & 15, ty = tid >> 4;
    float acc[4][4] = {};
    for (int k0 = kb; k0 < kb + IS / KSPL; k0 += 16) {
        {
            int m = tid >> 2, kk = (tid & 3) << 2;
            float4 v = *reinterpret_cast<const float4*>(&ctx[m * IS + k0 + kk]);
            As[m][kk] = v.x; As[m][kk + 1] = v.y; As[m][kk + 2] = v.z; As[m][kk + 3] = v.w;
        }
        {
            int n = tid >> 2, kk = (tid & 3) << 2;
            float4 v = *reinterpret_cast<const float4*>(&W[(size_t)(n0 + n) * ws + k0 + kk]);
            Ws[kk][n] = v.x; Ws[kk + 1][n] = v.y; Ws[kk + 2][n] = v.z; Ws[kk + 3][n] = v.w;
        }
        __syncthreads();
#pragma unroll
        for (int kk = 0; kk < 16; kk++) {
            float a[4];
#pragma unroll
            for (int i = 0; i < 4; i++) a[i] = As[ty * 4 + i][kk];
            float4 bv = *reinterpret_cast<const float4*>(&Ws[kk][tx * 4]);
            float b[4] = {bv.x, bv.y, bv.z, bv.w};
#pragma unroll
            for (int i = 0; i < 4; i++)
#pragma unroll
                for (int j = 0; j < 4; j++) acc[i][j] += a[i] * b[j];
        }
        __syncthreads();
    }
    float* pp = g_part + ((size_t)z * KSPL + blockIdx.y) * (NB * IS);
#pragma unroll
    for (int i = 0; i < 4; i++)
#pragma unroll
        for (int j = 0; j < 4; j++)
            pp[(ty * 4 + i) * IS + n0 + tx * 4 + j] = acc[i][j];
}

__global__ void redUC_kernel(const float* __restrict__ Ub, const float* __restrict__ encb) {
    int i = blockIdx.x * 256 + threadIdx.x;
    float su = Ub[i & (IS - 1)], sc = encb[i & (IS - 1)];
#pragma unroll
    for (int zz = 0; zz < KSPL; zz++) {
        su += g_part[zz * (NB * IS) + i];
        sc += g_part[(KSPL + zz) * (NB * IS) + i];
    }
    g_u[i] = su;
    g_c2[i] = sc;
}

__global__ void __launch_bounds__(256) gemmskv_kernel(const float* __restrict__ W) {
    __shared__ float As[64][17];
    __shared__ float Ws[16][68];
    const int n0 = blockIdx.x * 64;
    const int kb = blockIdx.y * (IS / KSPL);
    const int tid = threadIdx.x;
    const int tx = tid & 15, ty = tid >> 4;
    float acc[4][4] = {};
    for (int k0 = kb; k0 < kb + IS / KSPL; k0 += 16) {
        {
            int m = tid >> 2, kk = (tid & 3) << 2;
            float4 v = *reinterpret_cast<const float4*>(&g_u[m * IS + k0 + kk]);
            As[m][kk] = v.x; As[m][kk + 1] = v.y; As[m][kk + 2] = v.z; As[m][kk + 3] = v.w;
        }
        {
            int k = tid >> 4, n4 = (tid & 15) << 2;
            float4 v = *reinterpret_cast<const float4*>(&W[(size_t)(k0 + k) * IS + n0 + n4]);
            *reinterpret_cast<float4*>(&Ws[k][n4]) = v;
        }
        __syncthreads();
#pragma unroll
        for (int kk = 0; kk < 16; kk++) {
            float a[4];
#pragma unroll
            for (int i = 0; i < 4; i++) a[i] = As[ty * 4 + i][kk];
            float4 bv = *reinterpret_cast<const float4*>(&Ws[kk][tx * 4]);
            float b[4] = {bv.x, bv.y, bv.z, bv.w};
#pragma unroll
            for (int i = 0; i < 4; i++)
#pragma unroll
                for (int j = 0; j < 4; j++) acc[i][j] += a[i] * b[j];
        }
        __syncthreads();
    }
    float* pp = g_part + (size_t)blockIdx.y * (NB * IS);
#pragma unroll
    for (int i = 0; i < 4; i++)
#pragma unroll
        for (int j = 0; j < 4; j++)
            pp[(ty * 4 + i) * IS + n0 + tx * 4 + j] = acc[i][j];
}

__global__ void redV_kernel() {
    int i = blockIdx.x * 256 + threadIdx.x;
    float s = 0.f;
#pragma unroll
    for (int zz = 0; zz < KSPL; zz++) s += g_part[zz * (NB * IS) + i];
    g_uv[i] = s;
}

// ================= attention -> Phi/Plo (no g_c: softmax shift-invariant) ====
__global__ void __launch_bounds__(256) attn_kernel(const float* __restrict__ wemb) {
    extern __shared__ float sw[];
    __shared__ float ssc[32];
    const int t = blockIdx.x;
    const int tid = threadIdx.x;
    const int seg = g_seg[t];
    {
        const float4* wt4 = reinterpret_cast<const float4*>(wemb + (size_t)t * LL * IS);
        float4* sw4 = reinterpret_cast<float4*>(sw);
        for (int i = tid; i < LL * IS / 4; i += 256) sw4[i] = wt4[i];
    }
    __syncthreads();
    const float* uvp = g_uv + seg * IS;
    const int wid = tid >> 5, lane = tid & 31;
    for (int l = wid; l < LL; l += 8) {
        float s = 0.f;
        const float* row = sw + l * IS;
        for (int k = lane; k < IS; k += 32) s += row[k] * uvp[k];
#pragma unroll
        for (int o = 16; o; o >>= 1) s += __shfl_xor_sync(0xffffffffu, s, o);
        if (lane == 0) ssc[l] = s;
    }
    __syncthreads();
    if (tid < 32) {
        float v = (lane < LL) ? ssc[lane] : -3.0e38f;
        float m = v;
#pragma unroll
        for (int o = 16; o; o >>= 1) m = fmaxf(m, __shfl_xor_sync(0xffffffffu, m, o));
        float e = (lane < LL) ? __expf(v - m) : 0.f;
        float s = e;
#pragma unroll
        for (int o = 16; o; o >>= 1) s += __shfl_xor_sync(0xffffffffu, s, o);
        if (lane < LL) ssc[lane] = e / s;
    }
    __syncthreads();
    float at[LL];
#pragma unroll
    for (int l = 0; l < LL; l++) at[l] = ssc[l];
    const int d0 = tid * 4;
    float acc[4] = {};
#pragma unroll
    for (int l = 0; l < LL; l++) {
        const float4 a = *reinterpret_cast<const float4*>(&sw[l * IS + d0]);
        acc[0] += at[l] * a.x; acc[1] += at[l] * a.y;
        acc[2] += at[l] * a.z; acc[3] += at[l] * a.w;
    }
    __nv_bfloat16 h[4];
#pragma unroll
    for (int q = 0; q < 4; q++) h[q] = __float2bfloat16(acc[q]);
    __nv_bfloat162* ph2 = reinterpret_cast<__nv_bfloat162*>(g_Phi + (size_t)t * IS + d0);
    ph2[0] = __nv_bfloat162(h[0], h[1]);
    ph2[1] = __nv_bfloat162(h[2], h[3]);
    __nv_bfloat162* pl2 = reinterpret_cast<__nv_bfloat162*>(g_Plo + (size_t)t * IS + d0);
    pl2[0] = __nv_bfloat162(__float2bfloat16(acc[0] - __bfloat162float(h[0])),
                            __float2bfloat16(acc[1] - __bfloat162float(h[1])));
    pl2[1] = __nv_bfloat162(__float2bfloat16(acc[2] - __bfloat162float(h[2])),
                            __float2bfloat16(acc[3] - __bfloat162float(h[3])));
}

// ================= mma GEMM: per-chunk [Ahi|Alo|Bhi|Blo], A/B-tile reuse =====
__global__ void __launch_bounds__(256) gemm_mma_kernel() {
    extern __shared__ __nv_bfloat16 smbuf[];
    const uint32_t sb = smem_u32(smbuf);
    const int tid = threadIdx.x, lane = tid & 31, w = tid >> 5;
    const int m0 = blockIdx.y * 128, n0 = blockIdx.x * 128;
    const int wm = (w & 1) * 64, wn = (w >> 1) * 32;
    const int lr = tid >> 1;
    const int lb = (tid & 1) * 64;
    const uint32_t lrow16 = (uint32_t)(lane & 15) * (SROW * 2);
    const uint32_t lhi = (uint32_t)(lane >> 4) * 16;
    float acc[4][4][4] = {};

    auto load_stage = [&](int j) {
        const int kk = j * KC;
        const __nv_bfloat16* Ah = g_Phi + (size_t)(m0 + lr) * IS + kk;
        const __nv_bfloat16* Al = g_Plo + (size_t)(m0 + lr) * IS + kk;
        const __nv_bfloat16* Bh = g_Bhi + (size_t)(n0 + lr) * IS + kk;
        const __nv_bfloat16* Bl = g_Blo + (size_t)(n0 + lr) * IS + kk;
        const uint32_t base = sb + (j & 1) * STG_BYTES + lr * (SROW * 2) + lb;
        const int eo = lb / 2;
#pragma unroll
        for (int c = 0; c < 4; c++) {
            cp16(base + 0 * TILE_BYTES + c * 16, Ah + eo + c * 8);
            cp16(base + 1 * TILE_BYTES + c * 16, Al + eo + c * 8);
            cp16(base + 2 * TILE_BYTES + c * 16, Bh + eo + c * 8);
            cp16(base + 3 * TILE_BYTES + c * 16, Bl + eo + c * 8);
        }
    };

    load_stage(0); CP_COMMIT();
    for (int i = 0; i < NCHUNK; i++) {
        if (i + 1 < NCHUNK) load_stage(i + 1);
        CP_COMMIT();
        CP_WAIT(1);                     // stage i resident; newest may be pending
        __syncthreads();
        const uint32_t sbase = sb + (i & 1) * STG_BYTES;
        const uint32_t sAh = sbase, sAl = sbase + TILE_BYTES;
        const uint32_t sBh = sbase + 2 * TILE_BYTES, sBl = sbase + 3 * TILE_BYTES;
#pragma unroll
        for (int k16 = 0; k16 < KC / 16; k16++) {
            const uint32_t kbyte = (uint32_t)k16 * 32;
            uint32_t bh[2][4], bl[2][4];
#pragma unroll
            for (int p = 0; p < 2; p++) {
                ldm4(bh[p], sBh + (wn + p * 16) * (SROW * 2) + lrow16 + kbyte + lhi);
                ldm4(bl[p], sBl + (wn + p * 16) * (SROW * 2) + lrow16 + kbyte + lhi);
            }
#pragma unroll
            for (int mt = 0; mt < 4; mt++) {
                uint32_t ah[4], al[4];
                ldm4(ah, sAh + (wm + mt * 16) * (SROW * 2) + lrow16 + kbyte + lhi);
                ldm4(al, sAl + (wm + mt * 16) * (SROW * 2) + lrow16 + kbyte + lhi);
#pragma unroll
                for (int nt = 0; nt < 4; nt++) {
                    uint32_t b0 = bh[nt >> 1][nt & 1], b1 = bh[nt >> 1][(nt & 1) + 2];
                    mma16816(acc[mt][nt], ah, b0, b1);                           // Ahi*Bhi
                    mma16816(acc[mt][nt], al, b0, b1);                           // Alo*Bhi
                    mma16816(acc[mt][nt], ah, bl[nt >> 1][nt & 1],
                             bl[nt >> 1][(nt & 1) + 2]);                         // Ahi*Blo
                }
            }
        }
        __syncthreads();
    }

#pragma unroll
    for (int mt = 0; mt < 4; mt++) {
        int m = m0 + wm + mt * 16 + (lane >> 2);
#pragma unroll
        for (int nt = 0; nt < 4; nt++) {
            int n = n0 + wn + nt * 8 + (lane & 3) * 2;
            if (m < TT)
                *reinterpret_cast<float2*>(&g_Hm[(size_t)m * IS + n]) =
                    make_float2(acc[mt][nt][0], acc[mt][nt][1]);
            if (m + 8 < TT)
                *reinterpret_cast<float2*>(&g_Hm[(size_t)(m + 8) * IS + n]) =
                    make_float2(acc[mt][nt][2], acc[mt][nt][3]);
        }
    }
}

// ---------------- LayerNorm(Hm + c2[seg]) + ragged scatter --------------------
__global__ void __launch_bounds__(256) ln_kernel(const float* __restrict__ gamma,
                                                 const float* __restrict__ beta,
                                                 float* __restrict__ out) {
    __shared__ float rs[8], rs2[8];
    __shared__ float hv[IS];
    const int t = blockIdx.x;
    const int tid = threadIdx.x;
    const int seg = g_seg[t];
    const float* hm = g_Hm + (size_t)t * IS;
    const float* c2 = g_c2 + (size_t)seg * IS;
    float s = 0.f, s2 = 0.f;
    for (int d = tid; d < IS; d += 256) {
        float v = hm[d] + c2[d];
        hv[d] = v;
        s += v; s2 += v * v;
    }
    const int wid = tid >> 5, lane = tid & 31;
#pragma unroll
    for (int o = 16; o; o >>= 1) {
        s  += __shfl_xor_sync(0xffffffffu, s, o);
        s2 += __shfl_xor_sync(0xffffffffu, s2, o);
    }
    if (lane == 0) { rs[wid] = s; rs2[wid] = s2; }
    __syncthreads();
    if (tid == 0) {
        float S = 0.f, S2 = 0.f;
        for (int w = 0; w < 8; w++) { S += rs[w]; S2 += rs2[w]; }
        rs[0] = S; rs2[0] = S2;
    }
    __syncthreads();
    const float mean = rs[0] * (1.0f / IS);
    const float var  = rs2[0] * (1.0f / IS) - mean * mean;
    const float inv  = rsqrtf(var + LNEPS);
    float* orow = out + ((size_t)(seg * MAXL + g_pos[t])) * IS;
    for (int d = tid; d < IS; d += 256)
        orow[d] = gamma[d] * (hv[d] - mean) * inv + beta[d];
}

// ---------------- launch ------------------------------------------------------
extern "C" void kernel_launch(void* const* d_in, const int* in_sizes, int n_in,
                              void* d_out, int out_size) {
    const float* ctx   = (const float*)d_in[0];
    const float* wemb  = (const float*)d_in[1];
    const int*   l_hs  = (const int*)  d_in[3];
    const float* U_w   = (const float*)d_in[n_in - 8];
    const float* U_b   = (const float*)d_in[n_in - 7];
    const float* V_w   = (const float*)d_in[n_in - 6];
    const float* enc_w = (const float*)d_in[n_in - 4];
    const float* enc_b = (const float*)d_in[n_in - 3];
    const float* gamma = (const float*)d_in[n_in - 2];
    const float* beta  = (const float*)d_in[n_in - 1];
    float* out = (float*)d_out;

    cudaFuncSetAttribute(attn_kernel, cudaFuncAttributeMaxDynamicSharedMemorySize, LL * IS * 4);
    cudaFuncSetAttribute(gemm_mma_kernel, cudaFuncAttributeMaxDynamicSharedMemorySize, SMEM_GEMM);

    // ordered so attn is launch #6 (profiled by ncu -s 5 -c 1)
    map_kernel<<<1, NB>>>(l_hs);                                        // 1
    gemmsk2_kernel<<<dim3(IS / 64, KSPL, 2), 256>>>(ctx, U_w, enc_w + IS); // 2
    redUC_kernel<<<(NB * IS) / 256, 256>>>(U_b, enc_b);                 // 3
    gemmskv_kernel<<<dim3(IS / 64, KSPL), 256>>>(V_w);                  // 4
    redV_kernel<<<(NB * IS) / 256, 256>>>();                            // 5
    attn_kernel<<<TT, 256, LL * IS * 4>>>(wemb);                        // 6  <- profiled
    wconv_kernel<<<(IS * IS + (TPAD - TT) * IS) / 256, 256>>>(enc_w);   // 7
    fill_kernel<<<(NB * MAXL * IS / 4) / 256, 256>>>((const float4*)beta, (float4*)out); // 8
    gemm_mma_kernel<<<dim3(IS / 128, TPAD / 128), 256, SMEM_GEMM>>>();  // 9
    ln_kernel<<<TT, 256>>>(gamma, beta, out);                           // 10
}